// round 11
// baseline (speedup 1.0000x reference)
#include <cuda_runtime.h>
#include <cuda_bf16.h>
#include <cuda_fp16.h>
#include <cstdint>
#include <math.h>

// Problem constants
#define BB 2
#define CC 64
#define HH 128
#define WW 128
#define HS 64          // downsampled H=W
#define LL 4096        // HS*HS
#define EE 1024        // CC*16 (4x4 patch)
#define LSQ (4096*4096)

// ---------------- scratch (device globals; no allocation allowed) -------------
__device__ float  g_bgD[BB*LL*CC];          // [b][l][c] fp32 (for norms)
__device__ __half g_bgDH[BB*LL*CC];         // fp16 hi
__device__ __half g_bgDL[BB*LL*CC];         // fp16 lo
__device__ __half g_fgTH[BB*CC*LL];         // [b][c][p] fp16 hi
__device__ __half g_fgTL[BB*CC*LL];         // fp16 lo
__device__ float  g_sq[BB*LL];
__device__ float  g_ninv[BB*LL];
__device__ int    g_maskP[BB*LL];           // indexed by permuted a = j*64+i
__device__ __half g_colsF[(size_t)BB*LL*EE];  // cols fp16, row a = j*64+i
__device__ float  g_bufA[(size_t)BB*LSQ];     // 134 MB
__device__ float  g_bufB[(size_t)BB*LSQ];     // 134 MB
__device__ __half g_softF[(size_t)BB*LSQ];    // softmax fp16 (67 MB)
__device__ float  g_outcol[(size_t)BB*LL*EE]; // row pp = x*64+y

// ---------------- prep kernels -----------------------------------------------
__global__ void k_fgT(const float* __restrict__ fg) {
    int t = blockIdx.x * blockDim.x + threadIdx.x;
    if (t >= BB*CC*LL) return;
    int p = t & 4095, c = (t >> 12) & 63, b = t >> 18;
    int y = p >> 6, x = p & 63;
    float v = fg[(((size_t)b*CC + c)*HH + 2*y)*WW + 2*x];
    __half h = __float2half(v);
    size_t o = ((size_t)b*CC + c)*LL + p;
    g_fgTH[o] = h;
    g_fgTL[o] = __float2half(v - __half2float(h));
}

__global__ void k_bgD(const float* __restrict__ bg) {
    int t = blockIdx.x * blockDim.x + threadIdx.x;
    if (t >= BB*LL*CC) return;
    int c = t & 63, l = (t >> 6) & 4095, b = t >> 18;
    int i = l >> 6, j = l & 63;
    float v = bg[(((size_t)b*CC + c)*HH + 2*i)*WW + 2*j];
    size_t o = ((size_t)b*LL + l)*CC + c;
    g_bgD[o] = v;
    __half h = __float2half(v);
    g_bgDH[o] = h;
    g_bgDL[o] = __float2half(v - __half2float(h));
}

// per-location sum of squares over channels (one warp per l)
__global__ void k_sq() {
    int gid = blockIdx.x * blockDim.x + threadIdx.x;
    int gw = gid >> 5;
    int lane = gid & 31;
    if (gw >= BB*LL) return;
    const float* row = g_bgD + (size_t)gw * CC;
    float v0 = row[lane], v1 = row[lane + 32];
    float s = v0*v0 + v1*v1;
    #pragma unroll
    for (int o = 16; o; o >>= 1) s += __shfl_xor_sync(0xffffffffu, s, o);
    if (lane == 0) g_sq[gw] = s;
}

// patch norms (3x3 window of sq) and mask flags (written permuted)
__global__ void k_normmask(const float* __restrict__ mask) {
    int t = blockIdx.x * blockDim.x + threadIdx.x;
    if (t >= BB*LL) return;
    int b = t >> 12, l = t & 4095;
    int i = l >> 6, j = l & 63;
    float ss = 0.f, ms = 0.f;
    for (int di = -1; di <= 1; di++) {
        int ii = i + di; if (ii < 0 || ii >= HS) continue;
        for (int dj = -1; dj <= 1; dj++) {
            int jj = j + dj; if (jj < 0 || jj >= HS) continue;
            ss += g_sq[b*LL + ii*HS + jj];
            ms += mask[((size_t)b*HH + 2*ii)*WW + 2*jj];
        }
    }
    g_ninv[t] = 1.f / fmaxf(sqrtf(ss), 1e-3f);
    g_maskP[b*LL + j*HS + i] = (ms == 0.f) ? 1 : 0;
}

// 4x4 stride-2 patches of full-res background, rows permuted: a = j*64+i
__global__ void k_cols(const float* __restrict__ bg) {
    int t = blockIdx.x * blockDim.x + threadIdx.x;
    if (t >= BB*LL*EE) return;
    int e = t & 1023;
    int a = (t >> 10) & 4095;
    int b = t >> 22;
    int j = a >> 6, i = a & 63;
    int c = e >> 4, ki = (e >> 2) & 3, kj = e & 3;
    int Y = 2*i - 1 + ki, X = 2*j - 1 + kj;
    float v = 0.f;
    if (Y >= 0 && Y < HH && X >= 0 && X < WW)
        v = bg[(((size_t)b*CC + c)*HH + Y)*WW + X];
    g_colsF[(size_t)t] = __float2half(v);
}

// ---------------- tensor-core helpers -----------------------------------------
__device__ __forceinline__ void ldsm_x4(uint32_t* r, uint32_t addr) {
    asm volatile("ldmatrix.sync.aligned.m8n8.x4.shared.b16 {%0,%1,%2,%3}, [%4];"
        : "=r"(r[0]), "=r"(r[1]), "=r"(r[2]), "=r"(r[3]) : "r"(addr));
}
__device__ __forceinline__ void ldsm_x4_t(uint32_t* r, uint32_t addr) {
    asm volatile("ldmatrix.sync.aligned.m8n8.x4.trans.shared.b16 {%0,%1,%2,%3}, [%4];"
        : "=r"(r[0]), "=r"(r[1]), "=r"(r[2]), "=r"(r[3]) : "r"(addr));
}
__device__ __forceinline__ void mma_f16(float* c, const uint32_t* a, const uint32_t* b) {
    asm volatile(
        "mma.sync.aligned.m16n8k16.row.col.f32.f16.f16.f32 "
        "{%0,%1,%2,%3}, {%4,%5,%6,%7}, {%8,%9}, {%0,%1,%2,%3};"
        : "+f"(c[0]), "+f"(c[1]), "+f"(c[2]), "+f"(c[3])
        : "r"(a[0]), "r"(a[1]), "r"(a[2]), "r"(a[3]), "r"(b[0]), "r"(b[1]));
}
__device__ __forceinline__ void cpa16(uint32_t s, const void* g) {
    asm volatile("cp.async.cg.shared.global [%0], [%1], 16;" :: "r"(s), "l"(g));
}

// ---------------- GEMM1 (tensor): S0[l,p] = sum_c bgD[l,c]*fgT[c,p] -> bufA ---
// fp16 hi/lo both operands, 3 MMAs (ah*bh + ah*bl + al*bh). K=64 in 2 k32 steps.
__global__ __launch_bounds__(256) void k_gemm1() {
    __shared__ __half sAh[128][40], sAl[128][40];
    __shared__ __half sBh[32][136], sBl[32][136];
    int b = blockIdx.z;
    const __half* AH = g_bgDH + (size_t)b*LL*CC;
    const __half* AL = g_bgDL + (size_t)b*LL*CC;
    const __half* BH = g_fgTH + (size_t)b*CC*LL;
    const __half* BL = g_fgTL + (size_t)b*CC*LL;
    float* Cm = g_bufA + (size_t)b*LSQ;

    int m0 = blockIdx.y * 128, n0 = blockIdx.x * 128;
    int tid = threadIdx.x;
    int lane = tid & 31, warp = tid >> 5;
    int wm = warp & 1, wn = warp >> 1;
    int lr = lane & 15, lc = lane >> 4;

    float acc[4][4][4];
    #pragma unroll
    for (int mt = 0; mt < 4; mt++) {
        #pragma unroll
        for (int nt = 0; nt < 4; nt++) {
            #pragma unroll
            for (int q = 0; q < 4; q++) acc[mt][nt][q] = 0.f;
        }
    }

    uint32_t bAh = (uint32_t)__cvta_generic_to_shared(&sAh[0][0]);
    uint32_t bAl = (uint32_t)__cvta_generic_to_shared(&sAl[0][0]);
    uint32_t bBh = (uint32_t)__cvta_generic_to_shared(&sBh[0][0]);
    uint32_t bBl = (uint32_t)__cvta_generic_to_shared(&sBl[0][0]);

    for (int k0 = 0; k0 < 64; k0 += 32) {
        __syncthreads();
        #pragma unroll
        for (int i = 0; i < 2; i++) {
            int cid = tid + i*256;                    // 0..511
            int m = cid >> 2, kc = (cid & 3) * 8;
            *(uint4*)&sAh[m][kc] = *(const uint4*)(AH + (size_t)(m0+m)*CC + k0 + kc);
            *(uint4*)&sAl[m][kc] = *(const uint4*)(AL + (size_t)(m0+m)*CC + k0 + kc);
            int kb = cid >> 4, nc = (cid & 15) * 8;
            *(uint4*)&sBh[kb][nc] = *(const uint4*)(BH + (size_t)(k0+kb)*LL + n0 + nc);
            *(uint4*)&sBl[kb][nc] = *(const uint4*)(BL + (size_t)(k0+kb)*LL + n0 + nc);
        }
        __syncthreads();

        #pragma unroll
        for (int kk = 0; kk < 32; kk += 16) {
            uint32_t ah[4][4], al[4][4], bh[4][2], bl[4][2];
            #pragma unroll
            for (int mt = 0; mt < 4; mt++) {
                uint32_t offa = (uint32_t)((wm*64 + mt*16 + lr) * 40 + kk + lc*8) * 2u;
                ldsm_x4(ah[mt], bAh + offa);
                ldsm_x4(al[mt], bAl + offa);
            }
            #pragma unroll
            for (int ntp = 0; ntp < 2; ntp++) {
                uint32_t offb = (uint32_t)((kk + lr) * 136 + wn*32 + ntp*16 + lc*8) * 2u;
                uint32_t rh[4], rl[4];
                ldsm_x4_t(rh, bBh + offb);
                ldsm_x4_t(rl, bBl + offb);
                bh[ntp*2][0] = rh[0]; bh[ntp*2][1] = rh[1];
                bh[ntp*2+1][0] = rh[2]; bh[ntp*2+1][1] = rh[3];
                bl[ntp*2][0] = rl[0]; bl[ntp*2][1] = rl[1];
                bl[ntp*2+1][0] = rl[2]; bl[ntp*2+1][1] = rl[3];
            }
            #pragma unroll
            for (int mt = 0; mt < 4; mt++) {
                #pragma unroll
                for (int nt = 0; nt < 4; nt++) {
                    mma_f16(acc[mt][nt], ah[mt], bh[nt]);
                    mma_f16(acc[mt][nt], ah[mt], bl[nt]);
                    mma_f16(acc[mt][nt], al[mt], bh[nt]);
                }
            }
        }
    }

    int g = lane >> 2, tig = lane & 3;
    #pragma unroll
    for (int mt = 0; mt < 4; mt++) {
        int row0 = m0 + wm*64 + mt*16 + g;
        #pragma unroll
        for (int nt = 0; nt < 4; nt++) {
            int col = n0 + wn*32 + nt*8 + tig*2;
            *(float2*)(Cm + (size_t)row0*LL + col)     = make_float2(acc[mt][nt][0], acc[mt][nt][1]);
            *(float2*)(Cm + (size_t)(row0+8)*LL + col) = make_float2(acc[mt][nt][2], acc[mt][nt][3]);
        }
    }
}

// ---------------- fused 27-tap + permutation (15-load form): bufA -> bufB -----
// All 27 taps have equal offsets in both coordinates: S[l+δ, p+δ] with
// δ = d+dj+64*di. Distinct δ: (d+dj)∈[-2,2] × di∈{-1,0,1} = 15 loads.
// Weight of a (d+dj) group: w = Σ_{d,dj with that sum, gates pass} ninv[l+d],
// independent of di. Same term set as the 27-tap version, re-associated.
// Output written permuted via the 32x32 shared transpose tile (as before).
__global__ void k_diagp() {
    __shared__ float tile[32][33];
    int z = blockIdx.z;
    int b = z >> 12;
    int jy = z & 4095;
    int j = jy >> 6, y = jy & 63;
    const float* S = g_bufA + (size_t)b*LSQ;
    float* D = g_bufB + (size_t)b*LSQ;
    int i0 = blockIdx.x * 32, x0 = blockIdx.y * 32;

    #pragma unroll
    for (int k = 0; k < 4; k++) {
        int i = i0 + threadIdx.y + k*8;
        int x = x0 + threadIdx.x;
        int l = i*64 + j;
        int p = y*64 + x;

        // 5 group weights for ddj = d+dj in [-2,2]
        float w[5] = {0.f, 0.f, 0.f, 0.f, 0.f};
        #pragma unroll
        for (int d = -1; d <= 1; d++) {
            int lcn = l + d, pcn = p + d;
            if (lcn < 0 || lcn >= LL || pcn < 0 || pcn >= LL) continue;
            int jc = lcn & 63, xc = pcn & 63;
            float nv = g_ninv[b*LL + lcn];
            #pragma unroll
            for (int dj = -1; dj <= 1; dj++) {
                if (jc + dj < 0 || jc + dj > 63 || xc + dj < 0 || xc + dj > 63) continue;
                w[d + dj + 2] += nv;
            }
        }

        float acc = 0.f;
        #pragma unroll
        for (int ddj = -2; ddj <= 2; ddj++) {
            float vs = 0.f;
            #pragma unroll
            for (int di = -1; di <= 1; di++) {
                int dd = ddj + 64*di;
                int l2 = l + dd, p2 = p + dd;
                if (l2 >= 0 && l2 < LL && p2 >= 0 && p2 < LL)
                    vs += S[(size_t)l2*LL + p2];
            }
            acc += w[ddj + 2] * vs;
        }
        tile[threadIdx.y + k*8][threadIdx.x] = acc;
    }
    __syncthreads();
    #pragma unroll
    for (int k = 0; k < 4; k++) {
        int x = x0 + threadIdx.y + k*8;
        D[(size_t)(x*64 + y)*LL + j*64 + i0 + threadIdx.x] =
            tile[threadIdx.x][threadIdx.y + k*8];
    }
}

// ---------------- fuse #2 + mask + softmax over u: bufB -> softF (fp16) -------
__global__ __launch_bounds__(256) void k_softmax() {
    __shared__ float srow[4096];
    __shared__ float sred[8];
    int v = blockIdx.x & 4095;
    int b = blockIdx.x >> 12;
    const float* S = g_bufB + (size_t)b*LSQ;
    __half* DH = g_softF + (size_t)b*LSQ;
    int tid = threadIdx.x;
    int lane = tid & 31, wid = tid >> 5;

    float lmax = -1e30f;
    for (int u = tid; u < 4096; u += 256) {
        float acc = S[(size_t)v*LL + u];
        if (v > 0    && u > 0)    acc += S[(size_t)(v-1)*LL + u - 1];
        if (v < 4095 && u < 4095) acc += S[(size_t)(v+1)*LL + u + 1];
        float val = g_maskP[b*LL + u] ? -1000.f : acc;
        val *= 10.f;
        srow[u] = val;
        lmax = fmaxf(lmax, val);
    }
    #pragma unroll
    for (int o = 16; o; o >>= 1) lmax = fmaxf(lmax, __shfl_xor_sync(0xffffffffu, lmax, o));
    if (lane == 0) sred[wid] = lmax;
    __syncthreads();
    if (tid == 0) {
        float m = sred[0];
        #pragma unroll
        for (int w = 1; w < 8; w++) m = fmaxf(m, sred[w]);
        sred[0] = m;
    }
    __syncthreads();
    float gmax = sred[0];
    __syncthreads();

    float lsum = 0.f;
    for (int u = tid; u < 4096; u += 256) {
        float e = __expf(srow[u] - gmax);
        srow[u] = e;
        lsum += e;
    }
    #pragma unroll
    for (int o = 16; o; o >>= 1) lsum += __shfl_xor_sync(0xffffffffu, lsum, o);
    if (lane == 0) sred[wid] = lsum;
    __syncthreads();
    if (tid == 0) {
        float s2 = 0.f;
        #pragma unroll
        for (int w = 0; w < 8; w++) s2 += sred[w];
        sred[0] = s2;
    }
    __syncthreads();
    float inv = 1.f / sred[0];
    for (int u = tid; u < 4096; u += 256)
        DH[(size_t)v*LL + u] = __float2half(srow[u] * inv);
}

// ---------------- GEMM2 (2-stage, 1 sync/iter): OutCol = soft @ cols ----------
// A = single fp16 softmax, B = single fp16 cols. 1 MMA per k16.
// CTA tile 128x128, k-step 32, 2-stage double buffer, 32KB static smem.
// Loop order: wait_group 0 -> sync -> issue next stage -> commit -> compute.
// XOR-swizzled tiles (no padding):
//   A: 128 rows x 64B; 16B chunk c at row m stored at c ^ ((m>>1)&3)
//   B: 32 rows x 256B; 16B chunk c at row k stored at c ^ (k&7)
#define G2_STG 16384u   // per-stage bytes: A 8192 + B 8192
__global__ __launch_bounds__(256) void k_gemm2() {
    __shared__ char smem[2*G2_STG];   // 32768 B
    uint32_t sb = (uint32_t)__cvta_generic_to_shared(smem);

    int b = blockIdx.z;
    const __half* Af = g_softF + (size_t)b*LSQ;
    const __half* Bf = g_colsF + (size_t)b*LL*EE;
    float* Cm = g_outcol + (size_t)b*LL*EE;

    int m0 = blockIdx.y * 128, n0 = blockIdx.x * 128;
    int tid = threadIdx.x;
    int lane = tid & 31, warp = tid >> 5;
    int wm = warp & 1, wn = warp >> 1;
    int lr = lane & 15, lc = lane >> 4;

    float acc[4][4][4];
    #pragma unroll
    for (int mt = 0; mt < 4; mt++) {
        #pragma unroll
        for (int nt = 0; nt < 4; nt++) {
            #pragma unroll
            for (int q = 0; q < 4; q++) acc[mt][nt][q] = 0.f;
        }
    }

    // per-thread load slots (2 chunks per matrix per thread, 512 chunks each)
    int c0 = tid, c1 = tid + 256;
    int mA0 = c0 >> 2, cA0 = c0 & 3;
    int mA1 = c1 >> 2, cA1 = c1 & 3;
    uint32_t dA0 = (uint32_t)(mA0*64 + (cA0 ^ ((mA0>>1)&3))*16);
    uint32_t dA1 = (uint32_t)(mA1*64 + (cA1 ^ ((mA1>>1)&3))*16);
    int kB0 = c0 >> 4, cB0 = c0 & 15;
    int kB1 = c1 >> 4, cB1 = c1 & 15;
    uint32_t dB0 = (uint32_t)(kB0*256 + (cB0 ^ (kB0&7))*16);
    uint32_t dB1 = (uint32_t)(kB1*256 + (cB1 ^ (kB1&7))*16);

    const int STEPS = LL / 32;   // 128

    // prologue: issue stage 0
    {
        cpa16(sb + dA0,          Af + (size_t)(m0+mA0)*LL + cA0*8);
        cpa16(sb + dA1,          Af + (size_t)(m0+mA1)*LL + cA1*8);
        cpa16(sb + 8192u + dB0,  Bf + (size_t)kB0*EE + n0 + cB0*8);
        cpa16(sb + 8192u + dB1,  Bf + (size_t)kB1*EE + n0 + cB1*8);
        asm volatile("cp.async.commit_group;");
    }

    for (int i = 0; i < STEPS; i++) {
        asm volatile("cp.async.wait_group 0;");
        __syncthreads();

        if (i + 1 < STEPS) {
            int k0 = (i + 1) * 32;
            uint32_t s = sb + (uint32_t)(((i + 1) & 1) * G2_STG);
            cpa16(s + dA0,          Af + (size_t)(m0+mA0)*LL + k0 + cA0*8);
            cpa16(s + dA1,          Af + (size_t)(m0+mA1)*LL + k0 + cA1*8);
            cpa16(s + 8192u + dB0,  Bf + (size_t)(k0+kB0)*EE + n0 + cB0*8);
            cpa16(s + 8192u + dB1,  Bf + (size_t)(k0+kB1)*EE + n0 + cB1*8);
            asm volatile("cp.async.commit_group;");
        }

        uint32_t st = sb + (uint32_t)((i & 1) * G2_STG);
        #pragma unroll
        for (int kk = 0; kk < 32; kk += 16) {
            uint32_t af[4][4], bfr[4][2];
            #pragma unroll
            for (int mt = 0; mt < 4; mt++) {
                int row = wm*64 + mt*16 + lr;
                int ca = (kk >> 3) + lc;
                uint32_t offa = (uint32_t)(row*64 + ((ca ^ ((row>>1)&3)))*16);
                ldsm_x4(af[mt], st + offa);
            }
            #pragma unroll
            for (int ntp = 0; ntp < 2; ntp++) {
                int krow = kk + lr;
                int cb = wn*4 + ntp*2 + lc;
                uint32_t offb = 8192u + (uint32_t)(krow*256 + ((cb ^ (krow&7)))*16);
                uint32_t rh[4];
                ldsm_x4_t(rh, st + offb);
                bfr[ntp*2][0] = rh[0]; bfr[ntp*2][1] = rh[1];
                bfr[ntp*2+1][0] = rh[2]; bfr[ntp*2+1][1] = rh[3];
            }
            #pragma unroll
            for (int mt = 0; mt < 4; mt++) {
                #pragma unroll
                for (int nt = 0; nt < 4; nt++) {
                    mma_f16(acc[mt][nt], af[mt], bfr[nt]);
                }
            }
        }
    }

    int g = lane >> 2, tig = lane & 3;
    #pragma unroll
    for (int mt = 0; mt < 4; mt++) {
        int row0 = m0 + wm*64 + mt*16 + g;
        #pragma unroll
        for (int nt = 0; nt < 4; nt++) {
            int col = n0 + wn*32 + nt*8 + tig*2;
            *(float2*)(Cm + (size_t)row0*EE + col)     = make_float2(acc[mt][nt][0], acc[mt][nt][1]);
            *(float2*)(Cm + (size_t)(row0+8)*EE + col) = make_float2(acc[mt][nt][2], acc[mt][nt][3]);
        }
    }
}

// ---------------- overlap-add (transposed conv gather) ------------------------
__global__ void k_overlap(float* __restrict__ out) {
    int idx = blockIdx.x * blockDim.x + threadIdx.x;
    if (idx >= BB*CC*HH*WW) return;
    int X = idx & 127, Y = (idx >> 7) & 127, c = (idx >> 14) & 63, b = idx >> 20;
    float acc = 0.f;
    int y0 = (Y + 1) >> 1;
    int x0 = (X + 1) >> 1;
    #pragma unroll
    for (int dy = 0; dy < 2; dy++) {
        int yc = y0 - dy;
        if (yc < 0 || yc >= 64) continue;
        int ki = Y + 1 - 2*yc;
        if (ki < 0 || ki > 3) continue;
        #pragma unroll
        for (int dx = 0; dx < 2; dx++) {
            int xc = x0 - dx;
            if (xc < 0 || xc >= 64) continue;
            int kj = X + 1 - 2*xc;
            if (kj < 0 || kj > 3) continue;
            acc += g_outcol[((size_t)b*LL + xc*64 + yc)*EE + c*16 + ki*4 + kj];
        }
    }
    out[idx] = acc;
}

// ---------------- launch -------------------------------------------------------
extern "C" void kernel_launch(void* const* d_in, const int* in_sizes, int n_in,
                              void* d_out, int out_size) {
    const float* fg   = (const float*)d_in[0];
    const float* bg   = (const float*)d_in[1];
    const float* mask = (const float*)d_in[2];
    float* out = (float*)d_out;

    k_fgT<<<2048, 256>>>(fg);
    k_bgD<<<2048, 256>>>(bg);
    k_sq<<<1024, 256>>>();
    k_normmask<<<32, 256>>>(mask);
    k_cols<<<32768, 256>>>(bg);

    k_gemm1<<<dim3(32, 32, BB), 256>>>();                 // tensor -> bufA
    k_diagp<<<dim3(2, 2, BB*4096), dim3(32, 8)>>>();      // bufA -> bufB (15-load, permuted)
    k_softmax<<<BB*4096, 256>>>();                        // bufB -> softF (fp16)
    k_gemm2<<<dim3(8, 32, BB), 256>>>();                  // 2-stage -> outcol
    k_overlap<<<8192, 256>>>(out);
}

// round 12
// speedup vs baseline: 1.0618x; 1.0618x over previous
#include <cuda_runtime.h>
#include <cuda_bf16.h>
#include <cuda_fp16.h>
#include <cstdint>
#include <math.h>

// Problem constants
#define BB 2
#define CC 64
#define HH 128
#define WW 128
#define HS 64          // downsampled H=W
#define LL 4096        // HS*HS
#define EE 1024        // CC*16 (4x4 patch)
#define LSQ (4096*4096)

// ---------------- scratch (device globals; no allocation allowed) -------------
__device__ float  g_bgD[BB*LL*CC];          // [b][l][c] fp32 (for norms)
__device__ __half g_bgDH[BB*LL*CC];         // fp16 hi
__device__ __half g_bgDL[BB*LL*CC];         // fp16 lo
__device__ __half g_fgTH[BB*CC*LL];         // [b][c][p] fp16 hi
__device__ __half g_fgTL[BB*CC*LL];         // fp16 lo
__device__ float  g_sq[BB*LL];
__device__ float  g_ninv[BB*LL];
__device__ int    g_maskP[BB*LL];           // indexed by permuted a = j*64+i
__device__ __half g_colsF[(size_t)BB*LL*EE];  // cols fp16, row a = j*64+i
__device__ float  g_bufA[(size_t)BB*LSQ];     // 134 MB
__device__ float  g_bufB[(size_t)BB*LSQ];     // 134 MB
__device__ __half g_softF[(size_t)BB*LSQ];    // softmax fp16 (67 MB)
__device__ __half g_outcolH[(size_t)BB*LL*EE]; // fp16 outcol, row pp = x*64+y

// ---------------- prep kernels -----------------------------------------------
__global__ void k_fgT(const float* __restrict__ fg) {
    int t = blockIdx.x * blockDim.x + threadIdx.x;
    if (t >= BB*CC*LL) return;
    int p = t & 4095, c = (t >> 12) & 63, b = t >> 18;
    int y = p >> 6, x = p & 63;
    float v = fg[(((size_t)b*CC + c)*HH + 2*y)*WW + 2*x];
    __half h = __float2half(v);
    size_t o = ((size_t)b*CC + c)*LL + p;
    g_fgTH[o] = h;
    g_fgTL[o] = __float2half(v - __half2float(h));
}

__global__ void k_bgD(const float* __restrict__ bg) {
    int t = blockIdx.x * blockDim.x + threadIdx.x;
    if (t >= BB*LL*CC) return;
    int c = t & 63, l = (t >> 6) & 4095, b = t >> 18;
    int i = l >> 6, j = l & 63;
    float v = bg[(((size_t)b*CC + c)*HH + 2*i)*WW + 2*j];
    size_t o = ((size_t)b*LL + l)*CC + c;
    g_bgD[o] = v;
    __half h = __float2half(v);
    g_bgDH[o] = h;
    g_bgDL[o] = __float2half(v - __half2float(h));
}

// per-location sum of squares over channels (one warp per l)
__global__ void k_sq() {
    int gid = blockIdx.x * blockDim.x + threadIdx.x;
    int gw = gid >> 5;
    int lane = gid & 31;
    if (gw >= BB*LL) return;
    const float* row = g_bgD + (size_t)gw * CC;
    float v0 = row[lane], v1 = row[lane + 32];
    float s = v0*v0 + v1*v1;
    #pragma unroll
    for (int o = 16; o; o >>= 1) s += __shfl_xor_sync(0xffffffffu, s, o);
    if (lane == 0) g_sq[gw] = s;
}

// patch norms (3x3 window of sq) and mask flags (written permuted)
__global__ void k_normmask(const float* __restrict__ mask) {
    int t = blockIdx.x * blockDim.x + threadIdx.x;
    if (t >= BB*LL) return;
    int b = t >> 12, l = t & 4095;
    int i = l >> 6, j = l & 63;
    float ss = 0.f, ms = 0.f;
    for (int di = -1; di <= 1; di++) {
        int ii = i + di; if (ii < 0 || ii >= HS) continue;
        for (int dj = -1; dj <= 1; dj++) {
            int jj = j + dj; if (jj < 0 || jj >= HS) continue;
            ss += g_sq[b*LL + ii*HS + jj];
            ms += mask[((size_t)b*HH + 2*ii)*WW + 2*jj];
        }
    }
    g_ninv[t] = 1.f / fmaxf(sqrtf(ss), 1e-3f);
    g_maskP[b*LL + j*HS + i] = (ms == 0.f) ? 1 : 0;
}

// 4x4 stride-2 patches of full-res background, rows permuted: a = j*64+i
__global__ void k_cols(const float* __restrict__ bg) {
    int t = blockIdx.x * blockDim.x + threadIdx.x;
    if (t >= BB*LL*EE) return;
    int e = t & 1023;
    int a = (t >> 10) & 4095;
    int b = t >> 22;
    int j = a >> 6, i = a & 63;
    int c = e >> 4, ki = (e >> 2) & 3, kj = e & 3;
    int Y = 2*i - 1 + ki, X = 2*j - 1 + kj;
    float v = 0.f;
    if (Y >= 0 && Y < HH && X >= 0 && X < WW)
        v = bg[(((size_t)b*CC + c)*HH + Y)*WW + X];
    g_colsF[(size_t)t] = __float2half(v);
}

// ---------------- tensor-core helpers -----------------------------------------
__device__ __forceinline__ void ldsm_x4(uint32_t* r, uint32_t addr) {
    asm volatile("ldmatrix.sync.aligned.m8n8.x4.shared.b16 {%0,%1,%2,%3}, [%4];"
        : "=r"(r[0]), "=r"(r[1]), "=r"(r[2]), "=r"(r[3]) : "r"(addr));
}
__device__ __forceinline__ void ldsm_x4_t(uint32_t* r, uint32_t addr) {
    asm volatile("ldmatrix.sync.aligned.m8n8.x4.trans.shared.b16 {%0,%1,%2,%3}, [%4];"
        : "=r"(r[0]), "=r"(r[1]), "=r"(r[2]), "=r"(r[3]) : "r"(addr));
}
__device__ __forceinline__ void mma_f16(float* c, const uint32_t* a, const uint32_t* b) {
    asm volatile(
        "mma.sync.aligned.m16n8k16.row.col.f32.f16.f16.f32 "
        "{%0,%1,%2,%3}, {%4,%5,%6,%7}, {%8,%9}, {%0,%1,%2,%3};"
        : "+f"(c[0]), "+f"(c[1]), "+f"(c[2]), "+f"(c[3])
        : "r"(a[0]), "r"(a[1]), "r"(a[2]), "r"(a[3]), "r"(b[0]), "r"(b[1]));
}
__device__ __forceinline__ void cpa16(uint32_t s, const void* g) {
    asm volatile("cp.async.cg.shared.global [%0], [%1], 16;" :: "r"(s), "l"(g));
}

// ---------------- GEMM1 (tensor): S0[l,p] = sum_c bgD[l,c]*fgT[c,p] -> bufA ---
// fp16 hi/lo both operands, 3 MMAs (ah*bh + ah*bl + al*bh). K=64 in 2 k32 steps.
__global__ __launch_bounds__(256) void k_gemm1() {
    __shared__ __half sAh[128][40], sAl[128][40];
    __shared__ __half sBh[32][136], sBl[32][136];
    int b = blockIdx.z;
    const __half* AH = g_bgDH + (size_t)b*LL*CC;
    const __half* AL = g_bgDL + (size_t)b*LL*CC;
    const __half* BH = g_fgTH + (size_t)b*CC*LL;
    const __half* BL = g_fgTL + (size_t)b*CC*LL;
    float* Cm = g_bufA + (size_t)b*LSQ;

    int m0 = blockIdx.y * 128, n0 = blockIdx.x * 128;
    int tid = threadIdx.x;
    int lane = tid & 31, warp = tid >> 5;
    int wm = warp & 1, wn = warp >> 1;
    int lr = lane & 15, lc = lane >> 4;

    float acc[4][4][4];
    #pragma unroll
    for (int mt = 0; mt < 4; mt++) {
        #pragma unroll
        for (int nt = 0; nt < 4; nt++) {
            #pragma unroll
            for (int q = 0; q < 4; q++) acc[mt][nt][q] = 0.f;
        }
    }

    uint32_t bAh = (uint32_t)__cvta_generic_to_shared(&sAh[0][0]);
    uint32_t bAl = (uint32_t)__cvta_generic_to_shared(&sAl[0][0]);
    uint32_t bBh = (uint32_t)__cvta_generic_to_shared(&sBh[0][0]);
    uint32_t bBl = (uint32_t)__cvta_generic_to_shared(&sBl[0][0]);

    for (int k0 = 0; k0 < 64; k0 += 32) {
        __syncthreads();
        #pragma unroll
        for (int i = 0; i < 2; i++) {
            int cid = tid + i*256;                    // 0..511
            int m = cid >> 2, kc = (cid & 3) * 8;
            *(uint4*)&sAh[m][kc] = *(const uint4*)(AH + (size_t)(m0+m)*CC + k0 + kc);
            *(uint4*)&sAl[m][kc] = *(const uint4*)(AL + (size_t)(m0+m)*CC + k0 + kc);
            int kb = cid >> 4, nc = (cid & 15) * 8;
            *(uint4*)&sBh[kb][nc] = *(const uint4*)(BH + (size_t)(k0+kb)*LL + n0 + nc);
            *(uint4*)&sBl[kb][nc] = *(const uint4*)(BL + (size_t)(k0+kb)*LL + n0 + nc);
        }
        __syncthreads();

        #pragma unroll
        for (int kk = 0; kk < 32; kk += 16) {
            uint32_t ah[4][4], al[4][4], bh[4][2], bl[4][2];
            #pragma unroll
            for (int mt = 0; mt < 4; mt++) {
                uint32_t offa = (uint32_t)((wm*64 + mt*16 + lr) * 40 + kk + lc*8) * 2u;
                ldsm_x4(ah[mt], bAh + offa);
                ldsm_x4(al[mt], bAl + offa);
            }
            #pragma unroll
            for (int ntp = 0; ntp < 2; ntp++) {
                uint32_t offb = (uint32_t)((kk + lr) * 136 + wn*32 + ntp*16 + lc*8) * 2u;
                uint32_t rh[4], rl[4];
                ldsm_x4_t(rh, bBh + offb);
                ldsm_x4_t(rl, bBl + offb);
                bh[ntp*2][0] = rh[0]; bh[ntp*2][1] = rh[1];
                bh[ntp*2+1][0] = rh[2]; bh[ntp*2+1][1] = rh[3];
                bl[ntp*2][0] = rl[0]; bl[ntp*2][1] = rl[1];
                bl[ntp*2+1][0] = rl[2]; bl[ntp*2+1][1] = rl[3];
            }
            #pragma unroll
            for (int mt = 0; mt < 4; mt++) {
                #pragma unroll
                for (int nt = 0; nt < 4; nt++) {
                    mma_f16(acc[mt][nt], ah[mt], bh[nt]);
                    mma_f16(acc[mt][nt], ah[mt], bl[nt]);
                    mma_f16(acc[mt][nt], al[mt], bh[nt]);
                }
            }
        }
    }

    int g = lane >> 2, tig = lane & 3;
    #pragma unroll
    for (int mt = 0; mt < 4; mt++) {
        int row0 = m0 + wm*64 + mt*16 + g;
        #pragma unroll
        for (int nt = 0; nt < 4; nt++) {
            int col = n0 + wn*32 + nt*8 + tig*2;
            *(float2*)(Cm + (size_t)row0*LL + col)     = make_float2(acc[mt][nt][0], acc[mt][nt][1]);
            *(float2*)(Cm + (size_t)(row0+8)*LL + col) = make_float2(acc[mt][nt][2], acc[mt][nt][3]);
        }
    }
}

// ---------------- fused 27-tap + permutation: bufA -> bufB (permuted) ---------
// (R10 form: high-MLP 27-tap gather; faster than the 15-load re-association.)
__global__ void k_diagp() {
    __shared__ float tile[32][33];
    int z = blockIdx.z;
    int b = z >> 12;
    int jy = z & 4095;
    int j = jy >> 6, y = jy & 63;
    const float* S = g_bufA + (size_t)b*LSQ;
    float* D = g_bufB + (size_t)b*LSQ;
    int i0 = blockIdx.x * 32, x0 = blockIdx.y * 32;

    #pragma unroll
    for (int k = 0; k < 4; k++) {
        int i = i0 + threadIdx.y + k*8;
        int x = x0 + threadIdx.x;
        int l = i*64 + j;
        int p = y*64 + x;
        float acc = 0.f;
        #pragma unroll
        for (int d = -1; d <= 1; d++) {
            int lcn = l + d, pcn = p + d;
            if (lcn < 0 || lcn >= LL || pcn < 0 || pcn >= LL) continue;
            int jc = lcn & 63, xc = pcn & 63;
            float inner = 0.f;
            #pragma unroll
            for (int dj = -1; dj <= 1; dj++) {
                if (jc + dj < 0 || jc + dj > 63 || xc + dj < 0 || xc + dj > 63) continue;
                #pragma unroll
                for (int di = -1; di <= 1; di++) {
                    int l2 = lcn + dj + 64*di;
                    int p2 = pcn + dj + 64*di;
                    if (l2 >= 0 && l2 < LL && p2 >= 0 && p2 < LL)
                        inner += S[(size_t)l2*LL + p2];
                }
            }
            acc += inner * g_ninv[b*LL + lcn];
        }
        tile[threadIdx.y + k*8][threadIdx.x] = acc;
    }
    __syncthreads();
    #pragma unroll
    for (int k = 0; k < 4; k++) {
        int x = x0 + threadIdx.y + k*8;
        D[(size_t)(x*64 + y)*LL + j*64 + i0 + threadIdx.x] =
            tile[threadIdx.x][threadIdx.y + k*8];
    }
}

// ---------------- fuse #2 + mask + softmax over u: bufB -> softF (fp16) -------
__global__ __launch_bounds__(256) void k_softmax() {
    __shared__ float srow[4096];
    __shared__ float sred[8];
    int v = blockIdx.x & 4095;
    int b = blockIdx.x >> 12;
    const float* S = g_bufB + (size_t)b*LSQ;
    __half* DH = g_softF + (size_t)b*LSQ;
    int tid = threadIdx.x;
    int lane = tid & 31, wid = tid >> 5;

    float lmax = -1e30f;
    for (int u = tid; u < 4096; u += 256) {
        float acc = S[(size_t)v*LL + u];
        if (v > 0    && u > 0)    acc += S[(size_t)(v-1)*LL + u - 1];
        if (v < 4095 && u < 4095) acc += S[(size_t)(v+1)*LL + u + 1];
        float val = g_maskP[b*LL + u] ? -1000.f : acc;
        val *= 10.f;
        srow[u] = val;
        lmax = fmaxf(lmax, val);
    }
    #pragma unroll
    for (int o = 16; o; o >>= 1) lmax = fmaxf(lmax, __shfl_xor_sync(0xffffffffu, lmax, o));
    if (lane == 0) sred[wid] = lmax;
    __syncthreads();
    if (tid == 0) {
        float m = sred[0];
        #pragma unroll
        for (int w = 1; w < 8; w++) m = fmaxf(m, sred[w]);
        sred[0] = m;
    }
    __syncthreads();
    float gmax = sred[0];
    __syncthreads();

    float lsum = 0.f;
    for (int u = tid; u < 4096; u += 256) {
        float e = __expf(srow[u] - gmax);
        srow[u] = e;
        lsum += e;
    }
    #pragma unroll
    for (int o = 16; o; o >>= 1) lsum += __shfl_xor_sync(0xffffffffu, lsum, o);
    if (lane == 0) sred[wid] = lsum;
    __syncthreads();
    if (tid == 0) {
        float s2 = 0.f;
        #pragma unroll
        for (int w = 0; w < 8; w++) s2 += sred[w];
        sred[0] = s2;
    }
    __syncthreads();
    float inv = 1.f / sred[0];
    for (int u = tid; u < 4096; u += 256)
        DH[(size_t)v*LL + u] = __float2half(srow[u] * inv);
}

// ---------------- GEMM2 (2-stage, 1 sync/iter): OutCol = soft @ cols ----------
// A = single fp16 softmax, B = single fp16 cols. 1 MMA per k16.
// Epilogue now stores fp16 (outcol |values| = O(1): softmax rows sum to 1).
#define G2_STG 16384u   // per-stage bytes: A 8192 + B 8192
__global__ __launch_bounds__(256) void k_gemm2() {
    __shared__ char smem[2*G2_STG];   // 32768 B
    uint32_t sb = (uint32_t)__cvta_generic_to_shared(smem);

    int b = blockIdx.z;
    const __half* Af = g_softF + (size_t)b*LSQ;
    const __half* Bf = g_colsF + (size_t)b*LL*EE;
    __half* Cm = g_outcolH + (size_t)b*LL*EE;

    int m0 = blockIdx.y * 128, n0 = blockIdx.x * 128;
    int tid = threadIdx.x;
    int lane = tid & 31, warp = tid >> 5;
    int wm = warp & 1, wn = warp >> 1;
    int lr = lane & 15, lc = lane >> 4;

    float acc[4][4][4];
    #pragma unroll
    for (int mt = 0; mt < 4; mt++) {
        #pragma unroll
        for (int nt = 0; nt < 4; nt++) {
            #pragma unroll
            for (int q = 0; q < 4; q++) acc[mt][nt][q] = 0.f;
        }
    }

    // per-thread load slots (2 chunks per matrix per thread, 512 chunks each)
    int c0 = tid, c1 = tid + 256;
    int mA0 = c0 >> 2, cA0 = c0 & 3;
    int mA1 = c1 >> 2, cA1 = c1 & 3;
    uint32_t dA0 = (uint32_t)(mA0*64 + (cA0 ^ ((mA0>>1)&3))*16);
    uint32_t dA1 = (uint32_t)(mA1*64 + (cA1 ^ ((mA1>>1)&3))*16);
    int kB0 = c0 >> 4, cB0 = c0 & 15;
    int kB1 = c1 >> 4, cB1 = c1 & 15;
    uint32_t dB0 = (uint32_t)(kB0*256 + (cB0 ^ (kB0&7))*16);
    uint32_t dB1 = (uint32_t)(kB1*256 + (cB1 ^ (kB1&7))*16);

    const int STEPS = LL / 32;   // 128

    // prologue: issue stage 0
    {
        cpa16(sb + dA0,          Af + (size_t)(m0+mA0)*LL + cA0*8);
        cpa16(sb + dA1,          Af + (size_t)(m0+mA1)*LL + cA1*8);
        cpa16(sb + 8192u + dB0,  Bf + (size_t)kB0*EE + n0 + cB0*8);
        cpa16(sb + 8192u + dB1,  Bf + (size_t)kB1*EE + n0 + cB1*8);
        asm volatile("cp.async.commit_group;");
    }

    for (int i = 0; i < STEPS; i++) {
        asm volatile("cp.async.wait_group 0;");
        __syncthreads();

        if (i + 1 < STEPS) {
            int k0 = (i + 1) * 32;
            uint32_t s = sb + (uint32_t)(((i + 1) & 1) * G2_STG);
            cpa16(s + dA0,          Af + (size_t)(m0+mA0)*LL + k0 + cA0*8);
            cpa16(s + dA1,          Af + (size_t)(m0+mA1)*LL + k0 + cA1*8);
            cpa16(s + 8192u + dB0,  Bf + (size_t)(k0+kB0)*EE + n0 + cB0*8);
            cpa16(s + 8192u + dB1,  Bf + (size_t)(k0+kB1)*EE + n0 + cB1*8);
            asm volatile("cp.async.commit_group;");
        }

        uint32_t st = sb + (uint32_t)((i & 1) * G2_STG);
        #pragma unroll
        for (int kk = 0; kk < 32; kk += 16) {
            uint32_t af[4][4], bfr[4][2];
            #pragma unroll
            for (int mt = 0; mt < 4; mt++) {
                int row = wm*64 + mt*16 + lr;
                int ca = (kk >> 3) + lc;
                uint32_t offa = (uint32_t)(row*64 + ((ca ^ ((row>>1)&3)))*16);
                ldsm_x4(af[mt], st + offa);
            }
            #pragma unroll
            for (int ntp = 0; ntp < 2; ntp++) {
                int krow = kk + lr;
                int cb = wn*4 + ntp*2 + lc;
                uint32_t offb = 8192u + (uint32_t)(krow*256 + ((cb ^ (krow&7)))*16);
                uint32_t rh[4];
                ldsm_x4_t(rh, st + offb);
                bfr[ntp*2][0] = rh[0]; bfr[ntp*2][1] = rh[1];
                bfr[ntp*2+1][0] = rh[2]; bfr[ntp*2+1][1] = rh[3];
            }
            #pragma unroll
            for (int mt = 0; mt < 4; mt++) {
                #pragma unroll
                for (int nt = 0; nt < 4; nt++) {
                    mma_f16(acc[mt][nt], af[mt], bfr[nt]);
                }
            }
        }
    }

    int g = lane >> 2, tig = lane & 3;
    #pragma unroll
    for (int mt = 0; mt < 4; mt++) {
        int row0 = m0 + wm*64 + mt*16 + g;
        #pragma unroll
        for (int nt = 0; nt < 4; nt++) {
            int col = n0 + wn*32 + nt*8 + tig*2;
            __half2 v0 = __floats2half2_rn(acc[mt][nt][0], acc[mt][nt][1]);
            __half2 v1 = __floats2half2_rn(acc[mt][nt][2], acc[mt][nt][3]);
            *(__half2*)(Cm + (size_t)row0*EE + col)     = v0;
            *(__half2*)(Cm + (size_t)(row0+8)*EE + col) = v1;
        }
    }
}

// ---------------- overlap-add (transposed conv gather, fp16 in) ---------------
__global__ void k_overlap(float* __restrict__ out) {
    int idx = blockIdx.x * blockDim.x + threadIdx.x;
    if (idx >= BB*CC*HH*WW) return;
    int X = idx & 127, Y = (idx >> 7) & 127, c = (idx >> 14) & 63, b = idx >> 20;
    float acc = 0.f;
    int y0 = (Y + 1) >> 1;
    int x0 = (X + 1) >> 1;
    #pragma unroll
    for (int dy = 0; dy < 2; dy++) {
        int yc = y0 - dy;
        if (yc < 0 || yc >= 64) continue;
        int ki = Y + 1 - 2*yc;
        if (ki < 0 || ki > 3) continue;
        #pragma unroll
        for (int dx = 0; dx < 2; dx++) {
            int xc = x0 - dx;
            if (xc < 0 || xc >= 64) continue;
            int kj = X + 1 - 2*xc;
            if (kj < 0 || kj > 3) continue;
            acc += __half2float(
                g_outcolH[((size_t)b*LL + xc*64 + yc)*EE + c*16 + ki*4 + kj]);
        }
    }
    out[idx] = acc;
}

// ---------------- launch -------------------------------------------------------
extern "C" void kernel_launch(void* const* d_in, const int* in_sizes, int n_in,
                              void* d_out, int out_size) {
    const float* fg   = (const float*)d_in[0];
    const float* bg   = (const float*)d_in[1];
    const float* mask = (const float*)d_in[2];
    float* out = (float*)d_out;

    k_fgT<<<2048, 256>>>(fg);
    k_bgD<<<2048, 256>>>(bg);
    k_sq<<<1024, 256>>>();
    k_normmask<<<32, 256>>>(mask);
    k_cols<<<32768, 256>>>(bg);

    k_gemm1<<<dim3(32, 32, BB), 256>>>();                 // tensor -> bufA
    k_diagp<<<dim3(2, 2, BB*4096), dim3(32, 8)>>>();      // bufA -> bufB (27-tap, permuted)
    k_softmax<<<BB*4096, 256>>>();                        // bufB -> softF (fp16)
    k_gemm2<<<dim3(8, 32, BB), 256>>>();                  // 2-stage -> outcolH (fp16)
    k_overlap<<<8192, 256>>>(out);
}

// round 14
// speedup vs baseline: 1.1689x; 1.1009x over previous
#include <cuda_runtime.h>
#include <cuda_bf16.h>
#include <cuda_fp16.h>
#include <cstdint>
#include <math.h>

// Problem constants
#define BB 2
#define CC 64
#define HH 128
#define WW 128
#define HS 64          // downsampled H=W
#define LL 4096        // HS*HS
#define EE 1024        // CC*16 (4x4 patch)
#define LSQ (4096*4096)

// ---------------- scratch (device globals; no allocation allowed) -------------
__device__ float  g_bgD[BB*LL*CC];          // [b][l][c] fp32 (for norms)
__device__ __half g_bgDH[BB*LL*CC];         // fp16 hi
__device__ __half g_bgDL[BB*LL*CC];         // fp16 lo
__device__ __half g_fgTH[BB*CC*LL];         // [b][c][p] fp16 hi
__device__ __half g_fgTL[BB*CC*LL];         // fp16 lo
__device__ float  g_sq[BB*LL];
__device__ float  g_ninv[BB*LL];
__device__ int    g_maskP[BB*LL];           // indexed by permuted a = j*64+i
__device__ __half g_colsF[(size_t)BB*LL*EE];  // cols fp16, [a][e]
__device__ float  g_bufA[(size_t)BB*LSQ];     // 134 MB
__device__ float  g_bufB[(size_t)BB*LSQ];     // 134 MB
__device__ __half g_softF[(size_t)BB*LSQ];    // softmax fp16 (67 MB)
__device__ __half g_outcolH[(size_t)BB*LL*EE]; // fp16 outcol, row pp = x*64+y

// ---------------- prep kernels -----------------------------------------------
__global__ void k_fgT(const float* __restrict__ fg) {
    int t = blockIdx.x * blockDim.x + threadIdx.x;
    if (t >= BB*CC*LL) return;
    int p = t & 4095, c = (t >> 12) & 63, b = t >> 18;
    int y = p >> 6, x = p & 63;
    float v = fg[(((size_t)b*CC + c)*HH + 2*y)*WW + 2*x];
    __half h = __float2half(v);
    size_t o = ((size_t)b*CC + c)*LL + p;
    g_fgTH[o] = h;
    g_fgTL[o] = __float2half(v - __half2float(h));
}

__global__ void k_bgD(const float* __restrict__ bg) {
    int t = blockIdx.x * blockDim.x + threadIdx.x;
    if (t >= BB*LL*CC) return;
    int c = t & 63, l = (t >> 6) & 4095, b = t >> 18;
    int i = l >> 6, j = l & 63;
    float v = bg[(((size_t)b*CC + c)*HH + 2*i)*WW + 2*j];
    size_t o = ((size_t)b*LL + l)*CC + c;
    g_bgD[o] = v;
    __half h = __float2half(v);
    g_bgDH[o] = h;
    g_bgDL[o] = __float2half(v - __half2float(h));
}

// per-location sum of squares over channels (one warp per l)
__global__ void k_sq() {
    int gid = blockIdx.x * blockDim.x + threadIdx.x;
    int gw = gid >> 5;
    int lane = gid & 31;
    if (gw >= BB*LL) return;
    const float* row = g_bgD + (size_t)gw * CC;
    float v0 = row[lane], v1 = row[lane + 32];
    float s = v0*v0 + v1*v1;
    #pragma unroll
    for (int o = 16; o; o >>= 1) s += __shfl_xor_sync(0xffffffffu, s, o);
    if (lane == 0) g_sq[gw] = s;
}

// patch norms (3x3 window of sq) and mask flags (written permuted)
__global__ void k_normmask(const float* __restrict__ mask) {
    int t = blockIdx.x * blockDim.x + threadIdx.x;
    if (t >= BB*LL) return;
    int b = t >> 12, l = t & 4095;
    int i = l >> 6, j = l & 63;
    float ss = 0.f, ms = 0.f;
    for (int di = -1; di <= 1; di++) {
        int ii = i + di; if (ii < 0 || ii >= HS) continue;
        for (int dj = -1; dj <= 1; dj++) {
            int jj = j + dj; if (jj < 0 || jj >= HS) continue;
            ss += g_sq[b*LL + ii*HS + jj];
            ms += mask[((size_t)b*HH + 2*ii)*WW + 2*jj];
        }
    }
    g_ninv[t] = 1.f / fmaxf(sqrtf(ss), 1e-3f);
    g_maskP[b*LL + j*HS + i] = (ms == 0.f) ? 1 : 0;
}

// 4x4 stride-2 patches of full-res background, rows permuted: a = j*64+i
__global__ void k_cols(const float* __restrict__ bg) {
    int t = blockIdx.x * blockDim.x + threadIdx.x;
    if (t >= BB*LL*EE) return;
    int e = t & 1023;
    int a = (t >> 10) & 4095;
    int b = t >> 22;
    int j = a >> 6, i = a & 63;
    int c = e >> 4, ki = (e >> 2) & 3, kj = e & 3;
    int Y = 2*i - 1 + ki, X = 2*j - 1 + kj;
    float v = 0.f;
    if (Y >= 0 && Y < HH && X >= 0 && X < WW)
        v = bg[(((size_t)b*CC + c)*HH + Y)*WW + X];
    g_colsF[(size_t)t] = __float2half(v);
}

// ---------------- tensor-core helpers -----------------------------------------
__device__ __forceinline__ void ldsm_x4(uint32_t* r, uint32_t addr) {
    asm volatile("ldmatrix.sync.aligned.m8n8.x4.shared.b16 {%0,%1,%2,%3}, [%4];"
        : "=r"(r[0]), "=r"(r[1]), "=r"(r[2]), "=r"(r[3]) : "r"(addr));
}
__device__ __forceinline__ void ldsm_x4_t(uint32_t* r, uint32_t addr) {
    asm volatile("ldmatrix.sync.aligned.m8n8.x4.trans.shared.b16 {%0,%1,%2,%3}, [%4];"
        : "=r"(r[0]), "=r"(r[1]), "=r"(r[2]), "=r"(r[3]) : "r"(addr));
}
__device__ __forceinline__ void mma_f16(float* c, const uint32_t* a, const uint32_t* b) {
    asm volatile(
        "mma.sync.aligned.m16n8k16.row.col.f32.f16.f16.f32 "
        "{%0,%1,%2,%3}, {%4,%5,%6,%7}, {%8,%9}, {%0,%1,%2,%3};"
        : "+f"(c[0]), "+f"(c[1]), "+f"(c[2]), "+f"(c[3])
        : "r"(a[0]), "r"(a[1]), "r"(a[2]), "r"(a[3]), "r"(b[0]), "r"(b[1]));
}
__device__ __forceinline__ void cpa16(uint32_t s, const void* g) {
    asm volatile("cp.async.cg.shared.global [%0], [%1], 16;" :: "r"(s), "l"(g));
}

// ---------------- GEMM1 (tensor): S0[l,p] = sum_c bgD[l,c]*fgT[c,p] -> bufA ---
// fp16 hi/lo both operands, 3 MMAs (ah*bh + ah*bl + al*bh). K=64 in 2 k32 steps.
__global__ __launch_bounds__(256) void k_gemm1() {
    __shared__ __half sAh[128][40], sAl[128][40];
    __shared__ __half sBh[32][136], sBl[32][136];
    int b = blockIdx.z;
    const __half* AH = g_bgDH + (size_t)b*LL*CC;
    const __half* AL = g_bgDL + (size_t)b*LL*CC;
    const __half* BH = g_fgTH + (size_t)b*CC*LL;
    const __half* BL = g_fgTL + (size_t)b*CC*LL;
    float* Cm = g_bufA + (size_t)b*LSQ;

    int m0 = blockIdx.y * 128, n0 = blockIdx.x * 128;
    int tid = threadIdx.x;
    int lane = tid & 31, warp = tid >> 5;
    int wm = warp & 1, wn = warp >> 1;
    int lr = lane & 15, lc = lane >> 4;

    float acc[4][4][4];
    #pragma unroll
    for (int mt = 0; mt < 4; mt++) {
        #pragma unroll
        for (int nt = 0; nt < 4; nt++) {
            #pragma unroll
            for (int q = 0; q < 4; q++) acc[mt][nt][q] = 0.f;
        }
    }

    uint32_t bAh = (uint32_t)__cvta_generic_to_shared(&sAh[0][0]);
    uint32_t bAl = (uint32_t)__cvta_generic_to_shared(&sAl[0][0]);
    uint32_t bBh = (uint32_t)__cvta_generic_to_shared(&sBh[0][0]);
    uint32_t bBl = (uint32_t)__cvta_generic_to_shared(&sBl[0][0]);

    for (int k0 = 0; k0 < 64; k0 += 32) {
        __syncthreads();
        #pragma unroll
        for (int i = 0; i < 2; i++) {
            int cid = tid + i*256;
            int m = cid >> 2, kc = (cid & 3) * 8;
            *(uint4*)&sAh[m][kc] = *(const uint4*)(AH + (size_t)(m0+m)*CC + k0 + kc);
            *(uint4*)&sAl[m][kc] = *(const uint4*)(AL + (size_t)(m0+m)*CC + k0 + kc);
            int kb = cid >> 4, nc = (cid & 15) * 8;
            *(uint4*)&sBh[kb][nc] = *(const uint4*)(BH + (size_t)(k0+kb)*LL + n0 + nc);
            *(uint4*)&sBl[kb][nc] = *(const uint4*)(BL + (size_t)(k0+kb)*LL + n0 + nc);
        }
        __syncthreads();

        #pragma unroll
        for (int kk = 0; kk < 32; kk += 16) {
            uint32_t ah[4][4], al[4][4], bh[4][2], bl[4][2];
            #pragma unroll
            for (int mt = 0; mt < 4; mt++) {
                uint32_t offa = (uint32_t)((wm*64 + mt*16 + lr) * 40 + kk + lc*8) * 2u;
                ldsm_x4(ah[mt], bAh + offa);
                ldsm_x4(al[mt], bAl + offa);
            }
            #pragma unroll
            for (int ntp = 0; ntp < 2; ntp++) {
                uint32_t offb = (uint32_t)((kk + lr) * 136 + wn*32 + ntp*16 + lc*8) * 2u;
                uint32_t rh[4], rl[4];
                ldsm_x4_t(rh, bBh + offb);
                ldsm_x4_t(rl, bBl + offb);
                bh[ntp*2][0] = rh[0]; bh[ntp*2][1] = rh[1];
                bh[ntp*2+1][0] = rh[2]; bh[ntp*2+1][1] = rh[3];
                bl[ntp*2][0] = rl[0]; bl[ntp*2][1] = rl[1];
                bl[ntp*2+1][0] = rl[2]; bl[ntp*2+1][1] = rl[3];
            }
            #pragma unroll
            for (int mt = 0; mt < 4; mt++) {
                #pragma unroll
                for (int nt = 0; nt < 4; nt++) {
                    mma_f16(acc[mt][nt], ah[mt], bh[nt]);
                    mma_f16(acc[mt][nt], ah[mt], bl[nt]);
                    mma_f16(acc[mt][nt], al[mt], bh[nt]);
                }
            }
        }
    }

    int g = lane >> 2, tig = lane & 3;
    #pragma unroll
    for (int mt = 0; mt < 4; mt++) {
        int row0 = m0 + wm*64 + mt*16 + g;
        #pragma unroll
        for (int nt = 0; nt < 4; nt++) {
            int col = n0 + wn*32 + nt*8 + tig*2;
            *(float2*)(Cm + (size_t)row0*LL + col)     = make_float2(acc[mt][nt][0], acc[mt][nt][1]);
            *(float2*)(Cm + (size_t)(row0+8)*LL + col) = make_float2(acc[mt][nt][2], acc[mt][nt][3]);
        }
    }
}

// ---------------- fused 27-tap + permutation: bufA -> bufB (permuted) ---------
// 4-outputs-per-thread form: all taps share offsets S[l+δ, p+δ+t]; a thread
// computing t=0..3 loads each of 15 rows once with 4 consecutive columns
// (60 independent scalar LDGs for 4 outputs vs 108 before). Gating identical
// to R10 semantics, same per-d grouping (only fp add reordering).
// blockDim (8, 32): tx = x-quad, ty = i.
__global__ void k_diagp() {
    __shared__ float tile[32][33];
    int z = blockIdx.z;
    int b = z >> 12;
    int jy = z & 4095;
    int j = jy >> 6, y = jy & 63;
    const float* S = g_bufA + (size_t)b*LSQ;
    float* D = g_bufB + (size_t)b*LSQ;
    int i0 = blockIdx.x * 32, x0 = blockIdx.y * 32;

    int tx = threadIdx.x;    // 0..7
    int ty = threadIdx.y;    // 0..31
    int i = i0 + ty;
    int xb = x0 + tx*4;
    int l = i*64 + j;
    int p = y*64 + xb;

    // ts[s+2][t] = sum over di of S[l+δ, p+δ+t], δ = s + 64*di (flat-bounded)
    float ts[5][4];
    #pragma unroll
    for (int s = 0; s < 5; s++) {
        #pragma unroll
        for (int t = 0; t < 4; t++) ts[s][t] = 0.f;
    }
    #pragma unroll
    for (int s = -2; s <= 2; s++) {
        #pragma unroll
        for (int di = -1; di <= 1; di++) {
            int dd = s + 64*di;
            int l2 = l + dd;
            if (l2 < 0 || l2 >= LL) continue;
            const float* row = S + (size_t)l2*LL;
            int pb = p + dd;
            #pragma unroll
            for (int t = 0; t < 4; t++) {
                int p2 = pb + t;
                if (p2 >= 0 && p2 < LL) ts[s+2][t] += row[p2];
            }
        }
    }

    float out[4] = {0.f, 0.f, 0.f, 0.f};
    #pragma unroll
    for (int d = -1; d <= 1; d++) {
        int lcn = l + d;
        if (lcn < 0 || lcn >= LL) continue;
        float nv = g_ninv[b*LL + lcn];
        int jc = lcn & 63;
        #pragma unroll
        for (int t = 0; t < 4; t++) {
            int pcn = p + t + d;
            if (pcn < 0 || pcn >= LL) continue;
            int xc = pcn & 63;
            float inner = 0.f;
            #pragma unroll
            for (int dj = -1; dj <= 1; dj++) {
                if (jc + dj < 0 || jc + dj > 63 || xc + dj < 0 || xc + dj > 63) continue;
                inner += ts[d + dj + 2][t];
            }
            out[t] += inner * nv;
        }
    }

    #pragma unroll
    for (int t = 0; t < 4; t++) tile[ty][tx*4 + t] = out[t];
    __syncthreads();

    int wtid = tx + ty*8;
    int il = wtid & 31;
    #pragma unroll
    for (int k = 0; k < 4; k++) {
        int xl = (wtid >> 5) + k*8;
        D[(size_t)((x0 + xl)*64 + y)*LL + j*64 + i0 + il] = tile[il][xl];
    }
}

// ---------------- fuse #2 + mask + softmax over u: bufB -> softF (fp16) -------
__global__ __launch_bounds__(256) void k_softmax() {
    __shared__ float srow[4096];
    __shared__ float sred[8];
    int v = blockIdx.x & 4095;
    int b = blockIdx.x >> 12;
    const float* S = g_bufB + (size_t)b*LSQ;
    __half* DH = g_softF + (size_t)b*LSQ;
    int tid = threadIdx.x;
    int lane = tid & 31, wid = tid >> 5;

    float lmax = -1e30f;
    for (int u = tid; u < 4096; u += 256) {
        float acc = S[(size_t)v*LL + u];
        if (v > 0    && u > 0)    acc += S[(size_t)(v-1)*LL + u - 1];
        if (v < 4095 && u < 4095) acc += S[(size_t)(v+1)*LL + u + 1];
        float val = g_maskP[b*LL + u] ? -1000.f : acc;
        val *= 10.f;
        srow[u] = val;
        lmax = fmaxf(lmax, val);
    }
    #pragma unroll
    for (int o = 16; o; o >>= 1) lmax = fmaxf(lmax, __shfl_xor_sync(0xffffffffu, lmax, o));
    if (lane == 0) sred[wid] = lmax;
    __syncthreads();
    if (tid == 0) {
        float m = sred[0];
        #pragma unroll
        for (int w = 1; w < 8; w++) m = fmaxf(m, sred[w]);
        sred[0] = m;
    }
    __syncthreads();
    float gmax = sred[0];
    __syncthreads();

    float lsum = 0.f;
    for (int u = tid; u < 4096; u += 256) {
        float e = __expf(srow[u] - gmax);
        srow[u] = e;
        lsum += e;
    }
    #pragma unroll
    for (int o = 16; o; o >>= 1) lsum += __shfl_xor_sync(0xffffffffu, lsum, o);
    if (lane == 0) sred[wid] = lsum;
    __syncthreads();
    if (tid == 0) {
        float s2 = 0.f;
        #pragma unroll
        for (int w = 0; w < 8; w++) s2 += sred[w];
        sred[0] = s2;
    }
    __syncthreads();
    float inv = 1.f / sred[0];
    for (int u = tid; u < 4096; u += 256)
        DH[(size_t)v*LL + u] = __float2half(srow[u] * inv);
}

// ---------------- GEMM2 (2-stage, 1 sync/iter): OutCol = soft @ cols ----------
// A = single fp16 softmax, B = single fp16 cols. 1 MMA per k16. fp16 epilogue.
#define G2_STG 16384u   // per-stage bytes: A 8192 + B 8192
__global__ __launch_bounds__(256) void k_gemm2() {
    __shared__ char smem[2*G2_STG];   // 32768 B
    uint32_t sb = (uint32_t)__cvta_generic_to_shared(smem);

    int b = blockIdx.z;
    const __half* Af = g_softF + (size_t)b*LSQ;
    const __half* Bf = g_colsF + (size_t)b*LL*EE;
    __half* Cm = g_outcolH + (size_t)b*LL*EE;

    int m0 = blockIdx.y * 128, n0 = blockIdx.x * 128;
    int tid = threadIdx.x;
    int lane = tid & 31, warp = tid >> 5;
    int wm = warp & 1, wn = warp >> 1;
    int lr = lane & 15, lc = lane >> 4;

    float acc[4][4][4];
    #pragma unroll
    for (int mt = 0; mt < 4; mt++) {
        #pragma unroll
        for (int nt = 0; nt < 4; nt++) {
            #pragma unroll
            for (int q = 0; q < 4; q++) acc[mt][nt][q] = 0.f;
        }
    }

    int c0 = tid, c1 = tid + 256;
    int mA0 = c0 >> 2, cA0 = c0 & 3;
    int mA1 = c1 >> 2, cA1 = c1 & 3;
    uint32_t dA0 = (uint32_t)(mA0*64 + (cA0 ^ ((mA0>>1)&3))*16);
    uint32_t dA1 = (uint32_t)(mA1*64 + (cA1 ^ ((mA1>>1)&3))*16);
    int kB0 = c0 >> 4, cB0 = c0 & 15;
    int kB1 = c1 >> 4, cB1 = c1 & 15;
    uint32_t dB0 = (uint32_t)(kB0*256 + (cB0 ^ (kB0&7))*16);
    uint32_t dB1 = (uint32_t)(kB1*256 + (cB1 ^ (kB1&7))*16);

    const int STEPS = LL / 32;   // 128

    {
        cpa16(sb + dA0,          Af + (size_t)(m0+mA0)*LL + cA0*8);
        cpa16(sb + dA1,          Af + (size_t)(m0+mA1)*LL + cA1*8);
        cpa16(sb + 8192u + dB0,  Bf + (size_t)kB0*EE + n0 + cB0*8);
        cpa16(sb + 8192u + dB1,  Bf + (size_t)kB1*EE + n0 + cB1*8);
        asm volatile("cp.async.commit_group;");
    }

    for (int i = 0; i < STEPS; i++) {
        asm volatile("cp.async.wait_group 0;");
        __syncthreads();

        if (i + 1 < STEPS) {
            int k0 = (i + 1) * 32;
            uint32_t s = sb + (uint32_t)(((i + 1) & 1) * G2_STG);
            cpa16(s + dA0,          Af + (size_t)(m0+mA0)*LL + k0 + cA0*8);
            cpa16(s + dA1,          Af + (size_t)(m0+mA1)*LL + k0 + cA1*8);
            cpa16(s + 8192u + dB0,  Bf + (size_t)(k0+kB0)*EE + n0 + cB0*8);
            cpa16(s + 8192u + dB1,  Bf + (size_t)(k0+kB1)*EE + n0 + cB1*8);
            asm volatile("cp.async.commit_group;");
        }

        uint32_t st = sb + (uint32_t)((i & 1) * G2_STG);
        #pragma unroll
        for (int kk = 0; kk < 32; kk += 16) {
            uint32_t af[4][4], bfr[4][2];
            #pragma unroll
            for (int mt = 0; mt < 4; mt++) {
                int row = wm*64 + mt*16 + lr;
                int ca = (kk >> 3) + lc;
                uint32_t offa = (uint32_t)(row*64 + ((ca ^ ((row>>1)&3)))*16);
                ldsm_x4(af[mt], st + offa);
            }
            #pragma unroll
            for (int ntp = 0; ntp < 2; ntp++) {
                int krow = kk + lr;
                int cb = wn*4 + ntp*2 + lc;
                uint32_t offb = 8192u + (uint32_t)(krow*256 + ((cb ^ (krow&7)))*16);
                uint32_t rh[4];
                ldsm_x4_t(rh, st + offb);
                bfr[ntp*2][0] = rh[0]; bfr[ntp*2][1] = rh[1];
                bfr[ntp*2+1][0] = rh[2]; bfr[ntp*2+1][1] = rh[3];
            }
            #pragma unroll
            for (int mt = 0; mt < 4; mt++) {
                #pragma unroll
                for (int nt = 0; nt < 4; nt++) {
                    mma_f16(acc[mt][nt], af[mt], bfr[nt]);
                }
            }
        }
    }

    int g = lane >> 2, tig = lane & 3;
    #pragma unroll
    for (int mt = 0; mt < 4; mt++) {
        int row0 = m0 + wm*64 + mt*16 + g;
        #pragma unroll
        for (int nt = 0; nt < 4; nt++) {
            int col = n0 + wn*32 + nt*8 + tig*2;
            __half2 v0 = __floats2half2_rn(acc[mt][nt][0], acc[mt][nt][1]);
            __half2 v1 = __floats2half2_rn(acc[mt][nt][2], acc[mt][nt][3]);
            *(__half2*)(Cm + (size_t)row0*EE + col)     = v0;
            *(__half2*)(Cm + (size_t)(row0+8)*EE + col) = v1;
        }
    }
}

// ---------------- overlap-add (transposed conv gather, fp16 in) ---------------
__global__ void k_overlap(float* __restrict__ out) {
    int idx = blockIdx.x * blockDim.x + threadIdx.x;
    if (idx >= BB*CC*HH*WW) return;
    int X = idx & 127, Y = (idx >> 7) & 127, c = (idx >> 14) & 63, b = idx >> 20;
    float acc = 0.f;
    int y0 = (Y + 1) >> 1;
    int x0 = (X + 1) >> 1;
    #pragma unroll
    for (int dy = 0; dy < 2; dy++) {
        int yc = y0 - dy;
        if (yc < 0 || yc >= 64) continue;
        int ki = Y + 1 - 2*yc;
        if (ki < 0 || ki > 3) continue;
        #pragma unroll
        for (int dx = 0; dx < 2; dx++) {
            int xc = x0 - dx;
            if (xc < 0 || xc >= 64) continue;
            int kj = X + 1 - 2*xc;
            if (kj < 0 || kj > 3) continue;
            acc += __half2float(
                g_outcolH[((size_t)b*LL + xc*64 + yc)*EE + c*16 + ki*4 + kj]);
        }
    }
    out[idx] = acc;
}

// ---------------- launch -------------------------------------------------------
extern "C" void kernel_launch(void* const* d_in, const int* in_sizes, int n_in,
                              void* d_out, int out_size) {
    const float* fg   = (const float*)d_in[0];
    const float* bg   = (const float*)d_in[1];
    const float* mask = (const float*)d_in[2];
    float* out = (float*)d_out;

    k_fgT<<<2048, 256>>>(fg);
    k_bgD<<<2048, 256>>>(bg);
    k_sq<<<1024, 256>>>();
    k_normmask<<<32, 256>>>(mask);
    k_cols<<<32768, 256>>>(bg);

    k_gemm1<<<dim3(32, 32, BB), 256>>>();                 // tensor -> bufA
    k_diagp<<<dim3(2, 2, BB*4096), dim3(8, 32)>>>();      // bufA -> bufB (4-wide taps)
    k_softmax<<<BB*4096, 256>>>();                        // bufB -> softF (fp16)
    k_gemm2<<<dim3(8, 32, BB), 256>>>();                  // 2-stage -> outcolH (fp16)
    k_overlap<<<8192, 256>>>(out);
}